// round 12
// baseline (speedup 1.0000x reference)
#include <cuda_runtime.h>
#include <cuda_fp16.h>
#include <stdint.h>

#define NNODES 50000
#define FDIM 36
#define EMAX 800000
// packed row: per node, 3 head-blocks x 32B (12 fp16 feat + fp32 logit + pad), padded to 128B
#define ROWU 32                 // uint32 per node row (128B, line-aligned)

// ---------------- persistent device scratch ----------------
__device__ __align__(128) uint32_t g_hpA[NNODES * ROWU];
__device__ __align__(128) uint32_t g_hpB[NNODES * ROWU];
__device__ __align__(16) float g_y[NNODES * FDIM];
__device__ __align__(16) float g_ald[NNODES * 4];
__device__ int g_deg[NNODES];
__device__ int g_rowstart[NNODES];
__device__ int g_rank[EMAX];
__device__ int g_col[EMAX];
__device__ int g_total;

__device__ __forceinline__ float lrelu(float x) { return fmaxf(x, 0.2f * x); }

__device__ __forceinline__ uint32_t pack2(float a, float b) {
    __half2 t = __floats2half2_rn(a, b);
    return *(uint32_t*)&t;
}
__device__ __forceinline__ float2 unpack2(uint32_t u) {
    __half2 t = *(__half2*)&u;
    return __half22float2(t);
}

// ---------------- CSR build ----------------
__global__ void zero_kernel() {
    int i = blockIdx.x * blockDim.x + threadIdx.x;
    if (i < NNODES) g_deg[i] = 0;
    if (i == 0) g_total = 0;
}

__global__ void count_kernel(const int* __restrict__ dst, int E) {
    int i = blockIdx.x * blockDim.x + threadIdx.x;
    if (i < E) g_rank[i] = atomicAdd(&g_deg[dst[i]], 1);
}

__global__ void assign_kernel() {
    int i = blockIdx.x * blockDim.x + threadIdx.x;
    int lane = threadIdx.x & 31;
    int v = (i < NNODES) ? g_deg[i] : 0;
    int x = v;
    #pragma unroll
    for (int off = 1; off < 32; off <<= 1) {
        int t = __shfl_up_sync(0xffffffffu, x, off);
        if (lane >= off) x += t;
    }
    int wsum = __shfl_sync(0xffffffffu, x, 31);
    int base = 0;
    if (lane == 31) base = atomicAdd(&g_total, wsum);
    base = __shfl_sync(0xffffffffu, base, 31);
    if (i < NNODES) g_rowstart[i] = base + x - v;
}

__global__ void scatter_kernel(const int* __restrict__ src, const int* __restrict__ dst, int E) {
    int i = blockIdx.x * blockDim.x + threadIdx.x;
    if (i < E) {
        int d = dst[i];
        g_col[g_rowstart[d] + g_rank[i]] = src[i];
    }
}

// ---------------- packed-row writer: h[36] + als[3] -> 3 x 32B blocks ----------------
__device__ __forceinline__ void write_packed_row(uint32_t* __restrict__ hout, int n,
                                                 const float* h, float als0, float als1, float als2) {
    uint32_t* rp = hout + (n << 5);
    #pragma unroll
    for (int hh = 0; hh < 3; hh++) {
        const float* f = h + 12 * hh;
        float als = (hh == 0) ? als0 : ((hh == 1) ? als1 : als2);
        uint4 q0, q1;
        q0.x = pack2(f[0], f[1]);  q0.y = pack2(f[2], f[3]);
        q0.z = pack2(f[4], f[5]);  q0.w = pack2(f[6], f[7]);
        q1.x = pack2(f[8], f[9]);  q1.y = pack2(f[10], f[11]);
        q1.z = __float_as_uint(als); q1.w = 0;
        *(uint4*)(rp + 8 * hh)     = q0;
        *(uint4*)(rp + 8 * hh + 4) = q1;
    }
}

// ---------------- layer-0 transform: h = x @ W0^T (in=24) ----------------
__global__ void transform0_kernel(const float* __restrict__ xin,
                                  const float* __restrict__ W,
                                  const float* __restrict__ a_src,
                                  const float* __restrict__ a_dst,
                                  uint32_t* __restrict__ hout) {
    __shared__ float sW[FDIM * 24];
    __shared__ float sas[FDIM], sad[FDIM];
    int tid = threadIdx.x;
    for (int i = tid; i < FDIM * 24; i += blockDim.x) sW[i] = W[i];
    if (tid < FDIM) { sas[tid] = a_src[tid]; sad[tid] = a_dst[tid]; }
    __syncthreads();
    int n = blockIdx.x * blockDim.x + tid;
    if (n >= NNODES) return;

    float yr[24];
    const float4* xv = (const float4*)(xin + n * 24);
    #pragma unroll
    for (int q = 0; q < 6; q++) {
        float4 v = xv[q];
        yr[4 * q] = v.x; yr[4 * q + 1] = v.y; yr[4 * q + 2] = v.z; yr[4 * q + 3] = v.w;
    }

    float h[FDIM];
    float als0 = 0, als1 = 0, als2 = 0, ald0 = 0, ald1 = 0, ald2 = 0;
    #pragma unroll
    for (int o = 0; o < FDIM; o++) {
        float a = 0;
        #pragma unroll
        for (int i = 0; i < 24; i++) a = fmaf(yr[i], sW[o * 24 + i], a);
        h[o] = a;
        float as = a * sas[o], av = a * sad[o];
        if (o < 12)      { als0 += as; ald0 += av; }
        else if (o < 24) { als1 += as; ald1 += av; }
        else             { als2 += as; ald2 += av; }
    }
    write_packed_row(hout, n, h, als0, als1, als2);
    *(float4*)&g_ald[n * 4] = make_float4(ald0, ald1, ald2, 0.f);
}

// ---------------- mid transform: h = y @ W^T (36 -> 36) ----------------
__global__ void transform_mid_kernel(const float* __restrict__ W,
                                     const float* __restrict__ a_src,
                                     const float* __restrict__ a_dst,
                                     uint32_t* __restrict__ hout) {
    __shared__ float sW[FDIM * FDIM];
    __shared__ float sas[FDIM], sad[FDIM];
    int tid = threadIdx.x;
    for (int i = tid; i < FDIM * FDIM; i += blockDim.x) sW[i] = W[i];
    if (tid < FDIM) { sas[tid] = a_src[tid]; sad[tid] = a_dst[tid]; }
    __syncthreads();
    int n = blockIdx.x * blockDim.x + tid;
    if (n >= NNODES) return;

    float yr[FDIM];
    const float4* yv = (const float4*)(g_y + n * FDIM);
    #pragma unroll
    for (int q = 0; q < 9; q++) {
        float4 v = yv[q];
        yr[4 * q] = v.x; yr[4 * q + 1] = v.y; yr[4 * q + 2] = v.z; yr[4 * q + 3] = v.w;
    }

    float h[FDIM];
    float als0 = 0, als1 = 0, als2 = 0, ald0 = 0, ald1 = 0, ald2 = 0;
    #pragma unroll
    for (int o = 0; o < FDIM; o++) {
        float a = 0;
        #pragma unroll
        for (int i = 0; i < FDIM; i++) a = fmaf(yr[i], sW[o * FDIM + i], a);
        h[o] = a;
        float as = a * sas[o], av = a * sad[o];
        if (o < 12)      { als0 += as; ald0 += av; }
        else if (o < 24) { als1 += as; ald1 += av; }
        else             { als2 += as; ald2 += av; }
    }
    write_packed_row(hout, n, h, als0, als1, als2);
    *(float4*)&g_ald[n * 4] = make_float4(ald0, ald1, ald2, 0.f);
}

// ---------------- 6-lane gather: lane = (head h, half q) ----------------
// half 0: features f0..f7 (first 16B of block) + scalar logit load
// half 1: features f8..f11 + logit (second 16B of block)
template <bool RELU, bool LAST>
__global__ void __launch_bounds__(384)
gather6_kernel(const uint32_t* __restrict__ hin,
               const float* __restrict__ bias) {
    __shared__ float sb[FDIM];
    int tid = threadIdx.x;
    if (RELU) {
        if (tid < FDIM) sb[tid] = bias[tid];
        __syncthreads();
    }

    int t = blockIdx.x * blockDim.x + tid;
    int n = t / 6;
    int sub = t - 6 * n;
    if (n >= NNODES) return;
    int h = sub >> 1;
    int half = sub & 1;

    int beg = g_rowstart[n];
    int end = beg + g_deg[n];
    float aldh = g_ald[n * 4 + h];
    int boff = 8 * h + 4 * half;      // uint32 offset of this lane's 16B chunk

    float acc[8];
    float s;

    if (half == 0) {
        // self
        {
            const uint32_t* p = hin + (n << 5);
            uint4 A = *(const uint4*)(p + boff);
            float lg = __uint_as_float(p[8 * h + 6]);
            float w = __expf(lrelu(lg + aldh));
            s = w;
            float2 f0 = unpack2(A.x), f1 = unpack2(A.y), f2 = unpack2(A.z), f3 = unpack2(A.w);
            acc[0] = w * f0.x; acc[1] = w * f0.y; acc[2] = w * f1.x; acc[3] = w * f1.y;
            acc[4] = w * f2.x; acc[5] = w * f2.y; acc[6] = w * f3.x; acc[7] = w * f3.y;
        }
        #pragma unroll 2
        for (int j = beg; j < end; j++) {
            int sn = g_col[j];
            const uint32_t* p = hin + (sn << 5);
            uint4 A = *(const uint4*)(p + boff);
            float lg = __uint_as_float(p[8 * h + 6]);
            float w = __expf(lrelu(lg + aldh));
            s += w;
            float2 f0 = unpack2(A.x), f1 = unpack2(A.y), f2 = unpack2(A.z), f3 = unpack2(A.w);
            acc[0] = fmaf(w, f0.x, acc[0]); acc[1] = fmaf(w, f0.y, acc[1]);
            acc[2] = fmaf(w, f1.x, acc[2]); acc[3] = fmaf(w, f1.y, acc[3]);
            acc[4] = fmaf(w, f2.x, acc[4]); acc[5] = fmaf(w, f2.y, acc[5]);
            acc[6] = fmaf(w, f3.x, acc[6]); acc[7] = fmaf(w, f3.y, acc[7]);
        }
    } else {
        // self
        {
            const uint32_t* p = hin + (n << 5);
            uint4 B = *(const uint4*)(p + boff);
            float w = __expf(lrelu(__uint_as_float(B.z) + aldh));
            s = w;
            float2 f4 = unpack2(B.x), f5 = unpack2(B.y);
            acc[0] = w * f4.x; acc[1] = w * f4.y; acc[2] = w * f5.x; acc[3] = w * f5.y;
        }
        #pragma unroll 2
        for (int j = beg; j < end; j++) {
            int sn = g_col[j];
            const uint32_t* p = hin + (sn << 5);
            uint4 B = *(const uint4*)(p + boff);
            float w = __expf(lrelu(__uint_as_float(B.z) + aldh));
            s += w;
            float2 f4 = unpack2(B.x), f5 = unpack2(B.y);
            acc[0] = fmaf(w, f4.x, acc[0]); acc[1] = fmaf(w, f4.y, acc[1]);
            acc[2] = fmaf(w, f5.x, acc[2]); acc[3] = fmaf(w, f5.y, acc[3]);
        }
    }

    float inv = 1.f / (s + 1e-16f);
    int fo = 12 * h + 8 * half;
    float* yr = g_y + n * FDIM + fo;
    if (RELU) {
        const float* b = sb + fo;
        if (half == 0) {
            *(float4*)yr       = make_float4(fmaxf(fmaf(acc[0], inv, b[0]), 0.f),
                                             fmaxf(fmaf(acc[1], inv, b[1]), 0.f),
                                             fmaxf(fmaf(acc[2], inv, b[2]), 0.f),
                                             fmaxf(fmaf(acc[3], inv, b[3]), 0.f));
            *(float4*)(yr + 4) = make_float4(fmaxf(fmaf(acc[4], inv, b[4]), 0.f),
                                             fmaxf(fmaf(acc[5], inv, b[5]), 0.f),
                                             fmaxf(fmaf(acc[6], inv, b[6]), 0.f),
                                             fmaxf(fmaf(acc[7], inv, b[7]), 0.f));
        } else {
            *(float4*)yr = make_float4(fmaxf(fmaf(acc[0], inv, b[0]), 0.f),
                                       fmaxf(fmaf(acc[1], inv, b[1]), 0.f),
                                       fmaxf(fmaf(acc[2], inv, b[2]), 0.f),
                                       fmaxf(fmaf(acc[3], inv, b[3]), 0.f));
        }
    } else {
        if (half == 0) {
            *(float4*)yr       = make_float4(acc[0] * inv, acc[1] * inv, acc[2] * inv, acc[3] * inv);
            *(float4*)(yr + 4) = make_float4(acc[4] * inv, acc[5] * inv, acc[6] * inv, acc[7] * inv);
        } else {
            *(float4*)yr = make_float4(acc[0] * inv, acc[1] * inv, acc[2] * inv, acc[3] * inv);
        }
    }
    (void)LAST;
}

// ---------------- final: head-mean + b3 + lin1 + lin2 ----------------
__global__ void final_kernel(const float* __restrict__ b3,
                             const float* __restrict__ lin1_w,
                             const float* __restrict__ lin1_b,
                             const float* __restrict__ lin2_w,
                             const float* __restrict__ lin2_b,
                             float* __restrict__ out) {
    __shared__ float sb[12], s1w[144], s1b[12], s2w[72], s2b[6];
    int tid = threadIdx.x;
    if (tid < 12) { sb[tid] = b3[tid]; s1b[tid] = lin1_b[tid]; }
    if (tid < 6) s2b[tid] = lin2_b[tid];
    for (int i = tid; i < 144; i += blockDim.x) s1w[i] = lin1_w[i];
    for (int i = tid; i < 72; i += blockDim.x) s2w[i] = lin2_w[i];
    __syncthreads();
    int n = blockIdx.x * blockDim.x + tid;
    if (n >= NNODES) return;

    float yv[FDIM];
    const float4* yp = (const float4*)(g_y + n * FDIM);
    #pragma unroll
    for (int q = 0; q < 9; q++) {
        float4 v = yp[q];
        yv[4 * q] = v.x; yv[4 * q + 1] = v.y; yv[4 * q + 2] = v.z; yv[4 * q + 3] = v.w;
    }

    float o12[12];
    #pragma unroll
    for (int o = 0; o < 12; o++)
        o12[o] = (yv[o] + yv[o + 12] + yv[o + 24]) * (1.f / 3.f) + sb[o];

    float tt[12];
    #pragma unroll
    for (int j = 0; j < 12; j++) {
        float a = s1b[j];
        #pragma unroll
        for (int k = 0; k < 12; k++) a = fmaf(o12[k], s1w[j * 12 + k], a);
        tt[j] = a;
    }
    float r[6];
    #pragma unroll
    for (int i = 0; i < 6; i++) {
        float a = s2b[i];
        #pragma unroll
        for (int j = 0; j < 12; j++) a = fmaf(tt[j], s2w[i * 12 + j], a);
        r[i] = a;
    }
    float2* ov = (float2*)(out + n * 6);
    ov[0] = make_float2(r[0], r[1]);
    ov[1] = make_float2(r[2], r[3]);
    ov[2] = make_float2(r[4], r[5]);
}

// ---------------- launch ----------------
extern "C" void kernel_launch(void* const* d_in, const int* in_sizes, int n_in,
                              void* d_out, int out_size) {
    const float* x = (const float*)d_in[0];
    const int* ei = (const int*)d_in[1];
    int E = in_sizes[1] / 2;
    const int* src = ei;
    const int* dst = ei + E;

    const float* W[4]   = {(const float*)d_in[2],  (const float*)d_in[6],
                           (const float*)d_in[10], (const float*)d_in[14]};
    const float* asr[4] = {(const float*)d_in[3],  (const float*)d_in[7],
                           (const float*)d_in[11], (const float*)d_in[15]};
    const float* adt[4] = {(const float*)d_in[4],  (const float*)d_in[8],
                           (const float*)d_in[12], (const float*)d_in[16]};
    const float* b[4]   = {(const float*)d_in[5],  (const float*)d_in[9],
                           (const float*)d_in[13], (const float*)d_in[17]};
    const float* lin1_w = (const float*)d_in[18];
    const float* lin1_b = (const float*)d_in[19];
    const float* lin2_w = (const float*)d_in[20];
    const float* lin2_b = (const float*)d_in[21];
    float* out = (float*)d_out;

    uint32_t* hA; cudaGetSymbolAddress((void**)&hA, g_hpA);
    uint32_t* hB; cudaGetSymbolAddress((void**)&hB, g_hpB);

    int nb = (NNODES + 255) / 256;
    int eb = (E + 255) / 256;
    zero_kernel<<<nb, 256>>>();
    count_kernel<<<eb, 256>>>(dst, E);
    assign_kernel<<<nb, 256>>>();
    scatter_kernel<<<eb, 256>>>(src, dst, E);

    transform0_kernel<<<nb, 256>>>(x, W[0], asr[0], adt[0], hA);

    int gb = (NNODES * 6 + 383) / 384;
    gather6_kernel<true, false><<<gb, 384>>>(hA, b[0]);
    transform_mid_kernel<<<nb, 256>>>(W[1], asr[1], adt[1], hB);
    gather6_kernel<true, false><<<gb, 384>>>(hB, b[1]);
    transform_mid_kernel<<<nb, 256>>>(W[2], asr[2], adt[2], hA);
    gather6_kernel<true, false><<<gb, 384>>>(hA, b[2]);
    transform_mid_kernel<<<nb, 256>>>(W[3], asr[3], adt[3], hB);
    gather6_kernel<false, true><<<gb, 384>>>(hB, nullptr);
    final_kernel<<<nb, 256>>>(b[3], lin1_w, lin1_b, lin2_w, lin2_b, out);
}

// round 13
// speedup vs baseline: 1.0352x; 1.0352x over previous
#include <cuda_runtime.h>
#include <cuda_fp16.h>
#include <stdint.h>

#define NNODES 50000
#define FDIM 36
#define EMAX 800000
// packed row: per node, 3 head-blocks x 32B (12 fp16 feat + fp32 logit + pad), padded to 128B
#define ROWU 32                 // uint32 per node row (128B, line-aligned)

// ---------------- persistent device scratch ----------------
__device__ __align__(128) uint32_t g_hpA[NNODES * ROWU];
__device__ __align__(128) uint32_t g_hpB[NNODES * ROWU];
__device__ __align__(16) float g_y[NNODES * FDIM];
__device__ __align__(16) float g_ald[NNODES * 4];
__device__ int g_deg[NNODES];
__device__ int g_rowstart[NNODES];
__device__ int g_rank[EMAX];
__device__ int g_col[EMAX];
__device__ int g_total;

__device__ __forceinline__ float lrelu(float x) { return fmaxf(x, 0.2f * x); }

__device__ __forceinline__ uint32_t pack2(float a, float b) {
    __half2 t = __floats2half2_rn(a, b);
    return *(uint32_t*)&t;
}
__device__ __forceinline__ float2 unpack2(uint32_t u) {
    __half2 t = *(__half2*)&u;
    return __half22float2(t);
}

// ---------------- CSR build ----------------
__global__ void zero_kernel() {
    int i = blockIdx.x * blockDim.x + threadIdx.x;
    if (i < NNODES) g_deg[i] = 0;
    if (i == 0) g_total = 0;
}

__global__ void count_kernel(const int* __restrict__ dst, int E) {
    int i = blockIdx.x * blockDim.x + threadIdx.x;
    if (i < E) g_rank[i] = atomicAdd(&g_deg[dst[i]], 1);
}

__global__ void assign_kernel() {
    int i = blockIdx.x * blockDim.x + threadIdx.x;
    int lane = threadIdx.x & 31;
    int v = (i < NNODES) ? g_deg[i] : 0;
    int x = v;
    #pragma unroll
    for (int off = 1; off < 32; off <<= 1) {
        int t = __shfl_up_sync(0xffffffffu, x, off);
        if (lane >= off) x += t;
    }
    int wsum = __shfl_sync(0xffffffffu, x, 31);
    int base = 0;
    if (lane == 31) base = atomicAdd(&g_total, wsum);
    base = __shfl_sync(0xffffffffu, base, 31);
    if (i < NNODES) g_rowstart[i] = base + x - v;
}

__global__ void scatter_kernel(const int* __restrict__ src, const int* __restrict__ dst, int E) {
    int i = blockIdx.x * blockDim.x + threadIdx.x;
    if (i < E) {
        int d = dst[i];
        g_col[g_rowstart[d] + g_rank[i]] = src[i];
    }
}

// ---------------- packed-row writer: h[36] + als[3] -> 3 x 32B blocks ----------------
__device__ __forceinline__ void write_packed_row(uint32_t* __restrict__ hout, int n,
                                                 const float* h, float als0, float als1, float als2) {
    uint32_t* rp = hout + (n << 5);
    #pragma unroll
    for (int hh = 0; hh < 3; hh++) {
        const float* f = h + 12 * hh;
        float als = (hh == 0) ? als0 : ((hh == 1) ? als1 : als2);
        uint4 q0, q1;
        q0.x = pack2(f[0], f[1]);  q0.y = pack2(f[2], f[3]);
        q0.z = pack2(f[4], f[5]);  q0.w = pack2(f[6], f[7]);
        q1.x = pack2(f[8], f[9]);  q1.y = pack2(f[10], f[11]);
        q1.z = __float_as_uint(als); q1.w = 0;
        *(uint4*)(rp + 8 * hh)     = q0;
        *(uint4*)(rp + 8 * hh + 4) = q1;
    }
}

// ---------------- layer-0 transform: h = x @ W0^T (in=24) ----------------
__global__ void transform0_kernel(const float* __restrict__ xin,
                                  const float* __restrict__ W,
                                  const float* __restrict__ a_src,
                                  const float* __restrict__ a_dst,
                                  uint32_t* __restrict__ hout) {
    __shared__ float sW[FDIM * 24];
    __shared__ float sas[FDIM], sad[FDIM];
    int tid = threadIdx.x;
    for (int i = tid; i < FDIM * 24; i += blockDim.x) sW[i] = W[i];
    if (tid < FDIM) { sas[tid] = a_src[tid]; sad[tid] = a_dst[tid]; }
    __syncthreads();
    int n = blockIdx.x * blockDim.x + tid;
    if (n >= NNODES) return;

    float yr[24];
    const float4* xv = (const float4*)(xin + n * 24);
    #pragma unroll
    for (int q = 0; q < 6; q++) {
        float4 v = xv[q];
        yr[4 * q] = v.x; yr[4 * q + 1] = v.y; yr[4 * q + 2] = v.z; yr[4 * q + 3] = v.w;
    }

    float h[FDIM];
    float als0 = 0, als1 = 0, als2 = 0, ald0 = 0, ald1 = 0, ald2 = 0;
    #pragma unroll
    for (int o = 0; o < FDIM; o++) {
        float a = 0;
        #pragma unroll
        for (int i = 0; i < 24; i++) a = fmaf(yr[i], sW[o * 24 + i], a);
        h[o] = a;
        float as = a * sas[o], av = a * sad[o];
        if (o < 12)      { als0 += as; ald0 += av; }
        else if (o < 24) { als1 += as; ald1 += av; }
        else             { als2 += as; ald2 += av; }
    }
    write_packed_row(hout, n, h, als0, als1, als2);
    *(float4*)&g_ald[n * 4] = make_float4(ald0, ald1, ald2, 0.f);
}

// ---------------- mid transform: h = y @ W^T (36 -> 36) ----------------
__global__ void transform_mid_kernel(const float* __restrict__ W,
                                     const float* __restrict__ a_src,
                                     const float* __restrict__ a_dst,
                                     uint32_t* __restrict__ hout) {
    __shared__ float sW[FDIM * FDIM];
    __shared__ float sas[FDIM], sad[FDIM];
    int tid = threadIdx.x;
    for (int i = tid; i < FDIM * FDIM; i += blockDim.x) sW[i] = W[i];
    if (tid < FDIM) { sas[tid] = a_src[tid]; sad[tid] = a_dst[tid]; }
    __syncthreads();
    int n = blockIdx.x * blockDim.x + tid;
    if (n >= NNODES) return;

    float yr[FDIM];
    const float4* yv = (const float4*)(g_y + n * FDIM);
    #pragma unroll
    for (int q = 0; q < 9; q++) {
        float4 v = yv[q];
        yr[4 * q] = v.x; yr[4 * q + 1] = v.y; yr[4 * q + 2] = v.z; yr[4 * q + 3] = v.w;
    }

    float h[FDIM];
    float als0 = 0, als1 = 0, als2 = 0, ald0 = 0, ald1 = 0, ald2 = 0;
    #pragma unroll
    for (int o = 0; o < FDIM; o++) {
        float a = 0;
        #pragma unroll
        for (int i = 0; i < FDIM; i++) a = fmaf(yr[i], sW[o * FDIM + i], a);
        h[o] = a;
        float as = a * sas[o], av = a * sad[o];
        if (o < 12)      { als0 += as; ald0 += av; }
        else if (o < 24) { als1 += as; ald1 += av; }
        else             { als2 += as; ald2 += av; }
    }
    write_packed_row(hout, n, h, als0, als1, als2);
    *(float4*)&g_ald[n * 4] = make_float4(ald0, ald1, ald2, 0.f);
}

// ---------------- warp-per-node gather: 4 edge-slots x 8 slices ----------------
// lane = (e<<3)|s : slot e handles edges beg+jb+e, slice s covers bytes [16s,16s+16)
// of the neighbor's 128B row. Odd slices hold the fp32 logit in .z.
template <bool RELU>
__global__ void __launch_bounds__(256)
gather_warp_kernel(const uint32_t* __restrict__ hin,
                   const float* __restrict__ bias) {
    __shared__ float sb[FDIM];
    int tid = threadIdx.x;
    if (RELU) {
        if (tid < FDIM) sb[tid] = bias[tid];
        __syncthreads();
    }

    int n = blockIdx.x * 8 + (tid >> 5);
    if (n >= NNODES) return;
    int lane = tid & 31;
    int e = lane >> 3;
    int s = lane & 7;

    int beg = g_rowstart[n];
    int deg = g_deg[n];
    float aldh = g_ald[n * 4 + (s >> 1)];   // s=6,7 -> pad slot (0)

    float acc[8];
    #pragma unroll
    for (int k = 0; k < 8; k++) acc[k] = 0.f;
    float s_acc = 0.f;

    // self loop (slot 0 only contributes)
    {
        uint4 A = *(const uint4*)(hin + (n << 5) + (s << 2));
        float w = __expf(lrelu(__uint_as_float(A.z) + aldh));
        float wp = __shfl_xor_sync(0xffffffffu, w, 1);
        w = (s & 1) ? w : wp;
        if (e != 0) w = 0.f;
        float2 f0 = unpack2(A.x), f1 = unpack2(A.y), f2 = unpack2(A.z), f3 = unpack2(A.w);
        acc[0] = w * f0.x; acc[1] = w * f0.y; acc[2] = w * f1.x; acc[3] = w * f1.y;
        acc[4] = w * f2.x; acc[5] = w * f2.y; acc[6] = w * f3.x; acc[7] = w * f3.y;
        if (s & 1) s_acc = w;
    }

    for (int jb = 0; jb < deg; jb += 4) {
        int idx = jb + e;
        bool valid = idx < deg;
        int j = beg + (valid ? idx : deg - 1);
        int sn = g_col[j];
        uint4 A = *(const uint4*)(hin + (sn << 5) + (s << 2));
        float w = __expf(lrelu(__uint_as_float(A.z) + aldh));
        float wp = __shfl_xor_sync(0xffffffffu, w, 1);
        w = (s & 1) ? w : wp;
        if (!valid) w = 0.f;
        float2 f0 = unpack2(A.x), f1 = unpack2(A.y), f2 = unpack2(A.z), f3 = unpack2(A.w);
        acc[0] = fmaf(w, f0.x, acc[0]); acc[1] = fmaf(w, f0.y, acc[1]);
        acc[2] = fmaf(w, f1.x, acc[2]); acc[3] = fmaf(w, f1.y, acc[3]);
        acc[4] = fmaf(w, f2.x, acc[4]); acc[5] = fmaf(w, f2.y, acc[5]);
        acc[6] = fmaf(w, f3.x, acc[6]); acc[7] = fmaf(w, f3.y, acc[7]);
        if (s & 1) s_acc += w;
    }

    // reduce across the 4 edge slots (lanes xor 8, 16 keep slice id)
    #pragma unroll
    for (int off = 8; off <= 16; off <<= 1) {
        #pragma unroll
        for (int k = 0; k < 8; k++) acc[k] += __shfl_xor_sync(0xffffffffu, acc[k], off);
        s_acc += __shfl_xor_sync(0xffffffffu, s_acc, off);
    }

    // denominator for this lane's head lives on the odd slice of the pair
    float den = __shfl_sync(0xffffffffu, s_acc, lane | 1);
    float inv = 1.f / (den + 1e-16f);

    if (e == 0 && s < 6) {
        int h = s >> 1;
        float* yr = g_y + n * FDIM + 12 * h;
        if ((s & 1) == 0) {
            if (RELU) {
                const float* b = sb + 12 * h;
                *(float4*)yr       = make_float4(fmaxf(fmaf(acc[0], inv, b[0]), 0.f),
                                                 fmaxf(fmaf(acc[1], inv, b[1]), 0.f),
                                                 fmaxf(fmaf(acc[2], inv, b[2]), 0.f),
                                                 fmaxf(fmaf(acc[3], inv, b[3]), 0.f));
                *(float4*)(yr + 4) = make_float4(fmaxf(fmaf(acc[4], inv, b[4]), 0.f),
                                                 fmaxf(fmaf(acc[5], inv, b[5]), 0.f),
                                                 fmaxf(fmaf(acc[6], inv, b[6]), 0.f),
                                                 fmaxf(fmaf(acc[7], inv, b[7]), 0.f));
            } else {
                *(float4*)yr       = make_float4(acc[0] * inv, acc[1] * inv, acc[2] * inv, acc[3] * inv);
                *(float4*)(yr + 4) = make_float4(acc[4] * inv, acc[5] * inv, acc[6] * inv, acc[7] * inv);
            }
        } else {
            if (RELU) {
                const float* b = sb + 12 * h + 8;
                *(float4*)(yr + 8) = make_float4(fmaxf(fmaf(acc[0], inv, b[0]), 0.f),
                                                 fmaxf(fmaf(acc[1], inv, b[1]), 0.f),
                                                 fmaxf(fmaf(acc[2], inv, b[2]), 0.f),
                                                 fmaxf(fmaf(acc[3], inv, b[3]), 0.f));
            } else {
                *(float4*)(yr + 8) = make_float4(acc[0] * inv, acc[1] * inv, acc[2] * inv, acc[3] * inv);
            }
        }
    }
}

// ---------------- final: head-mean + b3 + lin1 + lin2 ----------------
__global__ void final_kernel(const float* __restrict__ b3,
                             const float* __restrict__ lin1_w,
                             const float* __restrict__ lin1_b,
                             const float* __restrict__ lin2_w,
                             const float* __restrict__ lin2_b,
                             float* __restrict__ out) {
    __shared__ float sb[12], s1w[144], s1b[12], s2w[72], s2b[6];
    int tid = threadIdx.x;
    if (tid < 12) { sb[tid] = b3[tid]; s1b[tid] = lin1_b[tid]; }
    if (tid < 6) s2b[tid] = lin2_b[tid];
    for (int i = tid; i < 144; i += blockDim.x) s1w[i] = lin1_w[i];
    for (int i = tid; i < 72; i += blockDim.x) s2w[i] = lin2_w[i];
    __syncthreads();
    int n = blockIdx.x * blockDim.x + tid;
    if (n >= NNODES) return;

    float yv[FDIM];
    const float4* yp = (const float4*)(g_y + n * FDIM);
    #pragma unroll
    for (int q = 0; q < 9; q++) {
        float4 v = yp[q];
        yv[4 * q] = v.x; yv[4 * q + 1] = v.y; yv[4 * q + 2] = v.z; yv[4 * q + 3] = v.w;
    }

    float o12[12];
    #pragma unroll
    for (int o = 0; o < 12; o++)
        o12[o] = (yv[o] + yv[o + 12] + yv[o + 24]) * (1.f / 3.f) + sb[o];

    float tt[12];
    #pragma unroll
    for (int j = 0; j < 12; j++) {
        float a = s1b[j];
        #pragma unroll
        for (int k = 0; k < 12; k++) a = fmaf(o12[k], s1w[j * 12 + k], a);
        tt[j] = a;
    }
    float r[6];
    #pragma unroll
    for (int i = 0; i < 6; i++) {
        float a = s2b[i];
        #pragma unroll
        for (int j = 0; j < 12; j++) a = fmaf(tt[j], s2w[i * 12 + j], a);
        r[i] = a;
    }
    float2* ov = (float2*)(out + n * 6);
    ov[0] = make_float2(r[0], r[1]);
    ov[1] = make_float2(r[2], r[3]);
    ov[2] = make_float2(r[4], r[5]);
}

// ---------------- launch ----------------
extern "C" void kernel_launch(void* const* d_in, const int* in_sizes, int n_in,
                              void* d_out, int out_size) {
    const float* x = (const float*)d_in[0];
    const int* ei = (const int*)d_in[1];
    int E = in_sizes[1] / 2;
    const int* src = ei;
    const int* dst = ei + E;

    const float* W[4]   = {(const float*)d_in[2],  (const float*)d_in[6],
                           (const float*)d_in[10], (const float*)d_in[14]};
    const float* asr[4] = {(const float*)d_in[3],  (const float*)d_in[7],
                           (const float*)d_in[11], (const float*)d_in[15]};
    const float* adt[4] = {(const float*)d_in[4],  (const float*)d_in[8],
                           (const float*)d_in[12], (const float*)d_in[16]};
    const float* b[4]   = {(const float*)d_in[5],  (const float*)d_in[9],
                           (const float*)d_in[13], (const float*)d_in[17]};
    const float* lin1_w = (const float*)d_in[18];
    const float* lin1_b = (const float*)d_in[19];
    const float* lin2_w = (const float*)d_in[20];
    const float* lin2_b = (const float*)d_in[21];
    float* out = (float*)d_out;

    uint32_t* hA; cudaGetSymbolAddress((void**)&hA, g_hpA);
    uint32_t* hB; cudaGetSymbolAddress((void**)&hB, g_hpB);

    int nb = (NNODES + 255) / 256;
    int eb = (E + 255) / 256;
    zero_kernel<<<nb, 256>>>();
    count_kernel<<<eb, 256>>>(dst, E);
    assign_kernel<<<nb, 256>>>();
    scatter_kernel<<<eb, 256>>>(src, dst, E);

    transform0_kernel<<<nb, 256>>>(x, W[0], asr[0], adt[0], hA);

    int gb = (NNODES + 7) / 8;      // warp per node, 8 warps per block
    gather_warp_kernel<true><<<gb, 256>>>(hA, b[0]);
    transform_mid_kernel<<<nb, 256>>>(W[1], asr[1], adt[1], hB);
    gather_warp_kernel<true><<<gb, 256>>>(hB, b[1]);
    transform_mid_kernel<<<nb, 256>>>(W[2], asr[2], adt[2], hA);
    gather_warp_kernel<true><<<gb, 256>>>(hA, b[2]);
    transform_mid_kernel<<<nb, 256>>>(W[3], asr[3], adt[3], hB);
    gather_warp_kernel<false><<<gb, 256>>>(hB, nullptr);
    final_kernel<<<nb, 256>>>(b[3], lin1_w, lin1_b, lin2_w, lin2_b, out);
}

// round 14
// speedup vs baseline: 1.5029x; 1.4517x over previous
#include <cuda_runtime.h>
#include <cuda_fp16.h>
#include <stdint.h>

#define NNODES 50000
#define FDIM 36
#define EMAX 800000
// packed row: per node, 3 head-blocks x 32B (12 fp16 feat + fp32 logit + pad), padded to 128B
#define ROWU 32                 // uint32 per node row (128B, line-aligned)

// ---------------- persistent device scratch ----------------
__device__ __align__(128) uint32_t g_hpA[NNODES * ROWU];
__device__ __align__(128) uint32_t g_hpB[NNODES * ROWU];
__device__ __align__(16) float g_y[NNODES * FDIM];
__device__ __align__(16) float g_ald[NNODES * 4];
__device__ int g_deg[NNODES];
__device__ int g_rowstart[NNODES];
__device__ int g_rank[EMAX];
__device__ int g_col[EMAX];
__device__ int g_total;

__device__ __forceinline__ float lrelu(float x) { return fmaxf(x, 0.2f * x); }

__device__ __forceinline__ uint32_t pack2(float a, float b) {
    __half2 t = __floats2half2_rn(a, b);
    return *(uint32_t*)&t;
}
__device__ __forceinline__ float2 unpack2(uint32_t u) {
    __half2 t = *(__half2*)&u;
    return __half22float2(t);
}

// 256-bit global load (sm_100+): one LDG.E.256 for a 32B-aligned block
__device__ __forceinline__ void ldg256(const uint32_t* p,
                                       uint32_t& a0, uint32_t& a1, uint32_t& a2, uint32_t& a3,
                                       uint32_t& a4, uint32_t& a5, uint32_t& a6, uint32_t& a7) {
    asm volatile("ld.global.nc.v8.b32 {%0,%1,%2,%3,%4,%5,%6,%7}, [%8];"
                 : "=r"(a0), "=r"(a1), "=r"(a2), "=r"(a3),
                   "=r"(a4), "=r"(a5), "=r"(a6), "=r"(a7)
                 : "l"(p));
}

// ---------------- CSR build ----------------
__global__ void zero_kernel() {
    int i = blockIdx.x * blockDim.x + threadIdx.x;
    if (i < NNODES) g_deg[i] = 0;
    if (i == 0) g_total = 0;
}

__global__ void count_kernel(const int* __restrict__ dst, int E) {
    int i = blockIdx.x * blockDim.x + threadIdx.x;
    if (i < E) g_rank[i] = atomicAdd(&g_deg[dst[i]], 1);
}

__global__ void assign_kernel() {
    int i = blockIdx.x * blockDim.x + threadIdx.x;
    int lane = threadIdx.x & 31;
    int v = (i < NNODES) ? g_deg[i] : 0;
    int x = v;
    #pragma unroll
    for (int off = 1; off < 32; off <<= 1) {
        int t = __shfl_up_sync(0xffffffffu, x, off);
        if (lane >= off) x += t;
    }
    int wsum = __shfl_sync(0xffffffffu, x, 31);
    int base = 0;
    if (lane == 31) base = atomicAdd(&g_total, wsum);
    base = __shfl_sync(0xffffffffu, base, 31);
    if (i < NNODES) g_rowstart[i] = base + x - v;
}

__global__ void scatter_kernel(const int* __restrict__ src, const int* __restrict__ dst, int E) {
    int i = blockIdx.x * blockDim.x + threadIdx.x;
    if (i < E) {
        int d = dst[i];
        g_col[g_rowstart[d] + g_rank[i]] = src[i];
    }
}

// ---------------- packed-row writer: h[36] + als[3] -> 3 x 32B blocks ----------------
__device__ __forceinline__ void write_packed_row(uint32_t* __restrict__ hout, int n,
                                                 const float* h, float als0, float als1, float als2) {
    uint32_t* rp = hout + (n << 5);
    #pragma unroll
    for (int hh = 0; hh < 3; hh++) {
        const float* f = h + 12 * hh;
        float als = (hh == 0) ? als0 : ((hh == 1) ? als1 : als2);
        uint4 q0, q1;
        q0.x = pack2(f[0], f[1]);  q0.y = pack2(f[2], f[3]);
        q0.z = pack2(f[4], f[5]);  q0.w = pack2(f[6], f[7]);
        q1.x = pack2(f[8], f[9]);  q1.y = pack2(f[10], f[11]);
        q1.z = __float_as_uint(als); q1.w = 0;
        *(uint4*)(rp + 8 * hh)     = q0;
        *(uint4*)(rp + 8 * hh + 4) = q1;
    }
}

// ---------------- layer-0 transform: h = x @ W0^T (in=24) ----------------
__global__ void transform0_kernel(const float* __restrict__ xin,
                                  const float* __restrict__ W,
                                  const float* __restrict__ a_src,
                                  const float* __restrict__ a_dst,
                                  uint32_t* __restrict__ hout) {
    __shared__ float sW[FDIM * 24];
    __shared__ float sas[FDIM], sad[FDIM];
    int tid = threadIdx.x;
    for (int i = tid; i < FDIM * 24; i += blockDim.x) sW[i] = W[i];
    if (tid < FDIM) { sas[tid] = a_src[tid]; sad[tid] = a_dst[tid]; }
    __syncthreads();
    int n = blockIdx.x * blockDim.x + tid;
    if (n >= NNODES) return;

    float yr[24];
    const float4* xv = (const float4*)(xin + n * 24);
    #pragma unroll
    for (int q = 0; q < 6; q++) {
        float4 v = xv[q];
        yr[4 * q] = v.x; yr[4 * q + 1] = v.y; yr[4 * q + 2] = v.z; yr[4 * q + 3] = v.w;
    }

    float h[FDIM];
    float als0 = 0, als1 = 0, als2 = 0, ald0 = 0, ald1 = 0, ald2 = 0;
    #pragma unroll
    for (int o = 0; o < FDIM; o++) {
        float a = 0;
        #pragma unroll
        for (int i = 0; i < 24; i++) a = fmaf(yr[i], sW[o * 24 + i], a);
        h[o] = a;
        float as = a * sas[o], av = a * sad[o];
        if (o < 12)      { als0 += as; ald0 += av; }
        else if (o < 24) { als1 += as; ald1 += av; }
        else             { als2 += as; ald2 += av; }
    }
    write_packed_row(hout, n, h, als0, als1, als2);
    *(float4*)&g_ald[n * 4] = make_float4(ald0, ald1, ald2, 0.f);
}

// ---------------- mid transform: h = y @ W^T (36 -> 36) ----------------
__global__ void transform_mid_kernel(const float* __restrict__ W,
                                     const float* __restrict__ a_src,
                                     const float* __restrict__ a_dst,
                                     uint32_t* __restrict__ hout) {
    __shared__ float sW[FDIM * FDIM];
    __shared__ float sas[FDIM], sad[FDIM];
    int tid = threadIdx.x;
    for (int i = tid; i < FDIM * FDIM; i += blockDim.x) sW[i] = W[i];
    if (tid < FDIM) { sas[tid] = a_src[tid]; sad[tid] = a_dst[tid]; }
    __syncthreads();
    int n = blockIdx.x * blockDim.x + tid;
    if (n >= NNODES) return;

    float yr[FDIM];
    const float4* yv = (const float4*)(g_y + n * FDIM);
    #pragma unroll
    for (int q = 0; q < 9; q++) {
        float4 v = yv[q];
        yr[4 * q] = v.x; yr[4 * q + 1] = v.y; yr[4 * q + 2] = v.z; yr[4 * q + 3] = v.w;
    }

    float h[FDIM];
    float als0 = 0, als1 = 0, als2 = 0, ald0 = 0, ald1 = 0, ald2 = 0;
    #pragma unroll
    for (int o = 0; o < FDIM; o++) {
        float a = 0;
        #pragma unroll
        for (int i = 0; i < FDIM; i++) a = fmaf(yr[i], sW[o * FDIM + i], a);
        h[o] = a;
        float as = a * sas[o], av = a * sad[o];
        if (o < 12)      { als0 += as; ald0 += av; }
        else if (o < 24) { als1 += as; ald1 += av; }
        else             { als2 += as; ald2 += av; }
    }
    write_packed_row(hout, n, h, als0, als1, als2);
    *(float4*)&g_ald[n * 4] = make_float4(ald0, ald1, ald2, 0.f);
}

// ---------------- head-per-lane aggregation: one 256-bit load per neighbor ----------------
__device__ __forceinline__ void head_aggregate(int n, int h, const uint32_t* __restrict__ hin,
                                               float acc[12], float& s) {
    int beg = g_rowstart[n];
    int end = beg + g_deg[n];
    float aldh = g_ald[n * 4 + h];
    int hoff = 8 * h;

    // self loop
    {
        uint32_t a0, a1, a2, a3, a4, a5, a6, a7;
        ldg256(hin + (n << 5) + hoff, a0, a1, a2, a3, a4, a5, a6, a7);
        float w = __expf(lrelu(__uint_as_float(a6) + aldh));
        s = w;
        float2 f0 = unpack2(a0), f1 = unpack2(a1), f2 = unpack2(a2), f3 = unpack2(a3);
        float2 f4 = unpack2(a4), f5 = unpack2(a5);
        acc[0] = w * f0.x;  acc[1] = w * f0.y;  acc[2] = w * f1.x;  acc[3] = w * f1.y;
        acc[4] = w * f2.x;  acc[5] = w * f2.y;  acc[6] = w * f3.x;  acc[7] = w * f3.y;
        acc[8] = w * f4.x;  acc[9] = w * f4.y;  acc[10] = w * f5.x; acc[11] = w * f5.y;
    }

    #pragma unroll 2
    for (int j = beg; j < end; j++) {
        int sn = g_col[j];
        uint32_t a0, a1, a2, a3, a4, a5, a6, a7;
        ldg256(hin + (sn << 5) + hoff, a0, a1, a2, a3, a4, a5, a6, a7);
        float w = __expf(lrelu(__uint_as_float(a6) + aldh));
        s += w;
        float2 f0 = unpack2(a0), f1 = unpack2(a1), f2 = unpack2(a2), f3 = unpack2(a3);
        float2 f4 = unpack2(a4), f5 = unpack2(a5);
        acc[0] = fmaf(w, f0.x, acc[0]);   acc[1] = fmaf(w, f0.y, acc[1]);
        acc[2] = fmaf(w, f1.x, acc[2]);   acc[3] = fmaf(w, f1.y, acc[3]);
        acc[4] = fmaf(w, f2.x, acc[4]);   acc[5] = fmaf(w, f2.y, acc[5]);
        acc[6] = fmaf(w, f3.x, acc[6]);   acc[7] = fmaf(w, f3.y, acc[7]);
        acc[8] = fmaf(w, f4.x, acc[8]);   acc[9] = fmaf(w, f4.y, acc[9]);
        acc[10] = fmaf(w, f5.x, acc[10]); acc[11] = fmaf(w, f5.y, acc[11]);
    }
}

// layers 0-2: gather + bias + relu -> g_y
__global__ void __launch_bounds__(384)
gather_head_kernel(const uint32_t* __restrict__ hin,
                   const float* __restrict__ bias) {
    __shared__ float sb[FDIM];
    int tid = threadIdx.x;
    if (tid < FDIM) sb[tid] = bias[tid];
    __syncthreads();

    int t = blockIdx.x * blockDim.x + tid;
    int n = t / 3;
    int h = t - 3 * n;
    if (n >= NNODES) return;

    float acc[12];
    float s;
    head_aggregate(n, h, hin, acc, s);

    float inv = 1.f / (s + 1e-16f);
    int fo = 12 * h;
    float* yr = g_y + n * FDIM + fo;
    const float* b = sb + fo;
    *(float4*)yr = make_float4(fmaxf(fmaf(acc[0], inv, b[0]), 0.f),
                               fmaxf(fmaf(acc[1], inv, b[1]), 0.f),
                               fmaxf(fmaf(acc[2], inv, b[2]), 0.f),
                               fmaxf(fmaf(acc[3], inv, b[3]), 0.f));
    *(float4*)(yr + 4) = make_float4(fmaxf(fmaf(acc[4], inv, b[4]), 0.f),
                                     fmaxf(fmaf(acc[5], inv, b[5]), 0.f),
                                     fmaxf(fmaf(acc[6], inv, b[6]), 0.f),
                                     fmaxf(fmaf(acc[7], inv, b[7]), 0.f));
    *(float4*)(yr + 8) = make_float4(fmaxf(fmaf(acc[8], inv, b[8]), 0.f),
                                     fmaxf(fmaf(acc[9], inv, b[9]), 0.f),
                                     fmaxf(fmaf(acc[10], inv, b[10]), 0.f),
                                     fmaxf(fmaf(acc[11], inv, b[11]), 0.f));
}

// layer 3: gather (no bias/relu) -> g_y
__global__ void __launch_bounds__(384)
gather_head_last_kernel(const uint32_t* __restrict__ hin) {
    int tid = threadIdx.x;
    int t = blockIdx.x * blockDim.x + tid;
    int n = t / 3;
    int h = t - 3 * n;
    if (n >= NNODES) return;

    float acc[12];
    float s;
    head_aggregate(n, h, hin, acc, s);

    float inv = 1.f / (s + 1e-16f);
    float* yr = g_y + n * FDIM + 12 * h;
    *(float4*)yr       = make_float4(acc[0] * inv, acc[1] * inv, acc[2] * inv, acc[3] * inv);
    *(float4*)(yr + 4) = make_float4(acc[4] * inv, acc[5] * inv, acc[6] * inv, acc[7] * inv);
    *(float4*)(yr + 8) = make_float4(acc[8] * inv, acc[9] * inv, acc[10] * inv, acc[11] * inv);
}

// ---------------- final: head-mean + b3 + lin1 + lin2 ----------------
__global__ void final_kernel(const float* __restrict__ b3,
                             const float* __restrict__ lin1_w,
                             const float* __restrict__ lin1_b,
                             const float* __restrict__ lin2_w,
                             const float* __restrict__ lin2_b,
                             float* __restrict__ out) {
    __shared__ float sb[12], s1w[144], s1b[12], s2w[72], s2b[6];
    int tid = threadIdx.x;
    if (tid < 12) { sb[tid] = b3[tid]; s1b[tid] = lin1_b[tid]; }
    if (tid < 6) s2b[tid] = lin2_b[tid];
    for (int i = tid; i < 144; i += blockDim.x) s1w[i] = lin1_w[i];
    for (int i = tid; i < 72; i += blockDim.x) s2w[i] = lin2_w[i];
    __syncthreads();
    int n = blockIdx.x * blockDim.x + tid;
    if (n >= NNODES) return;

    float yv[FDIM];
    const float4* yp = (const float4*)(g_y + n * FDIM);
    #pragma unroll
    for (int q = 0; q < 9; q++) {
        float4 v = yp[q];
        yv[4 * q] = v.x; yv[4 * q + 1] = v.y; yv[4 * q + 2] = v.z; yv[4 * q + 3] = v.w;
    }

    float o12[12];
    #pragma unroll
    for (int o = 0; o < 12; o++)
        o12[o] = (yv[o] + yv[o + 12] + yv[o + 24]) * (1.f / 3.f) + sb[o];

    float tt[12];
    #pragma unroll
    for (int j = 0; j < 12; j++) {
        float a = s1b[j];
        #pragma unroll
        for (int k = 0; k < 12; k++) a = fmaf(o12[k], s1w[j * 12 + k], a);
        tt[j] = a;
    }
    float r[6];
    #pragma unroll
    for (int i = 0; i < 6; i++) {
        float a = s2b[i];
        #pragma unroll
        for (int j = 0; j < 12; j++) a = fmaf(tt[j], s2w[i * 12 + j], a);
        r[i] = a;
    }
    float2* ov = (float2*)(out + n * 6);
    ov[0] = make_float2(r[0], r[1]);
    ov[1] = make_float2(r[2], r[3]);
    ov[2] = make_float2(r[4], r[5]);
}

// ---------------- launch ----------------
extern "C" void kernel_launch(void* const* d_in, const int* in_sizes, int n_in,
                              void* d_out, int out_size) {
    const float* x = (const float*)d_in[0];
    const int* ei = (const int*)d_in[1];
    int E = in_sizes[1] / 2;
    const int* src = ei;
    const int* dst = ei + E;

    const float* W[4]   = {(const float*)d_in[2],  (const float*)d_in[6],
                           (const float*)d_in[10], (const float*)d_in[14]};
    const float* asr[4] = {(const float*)d_in[3],  (const float*)d_in[7],
                           (const float*)d_in[11], (const float*)d_in[15]};
    const float* adt[4] = {(const float*)d_in[4],  (const float*)d_in[8],
                           (const float*)d_in[12], (const float*)d_in[16]};
    const float* b[4]   = {(const float*)d_in[5],  (const float*)d_in[9],
                           (const float*)d_in[13], (const float*)d_in[17]};
    const float* lin1_w = (const float*)d_in[18];
    const float* lin1_b = (const float*)d_in[19];
    const float* lin2_w = (const float*)d_in[20];
    const float* lin2_b = (const float*)d_in[21];
    float* out = (float*)d_out;

    uint32_t* hA; cudaGetSymbolAddress((void**)&hA, g_hpA);
    uint32_t* hB; cudaGetSymbolAddress((void**)&hB, g_hpB);

    int nb = (NNODES + 255) / 256;
    int eb = (E + 255) / 256;
    zero_kernel<<<nb, 256>>>();
    count_kernel<<<eb, 256>>>(dst, E);
    assign_kernel<<<nb, 256>>>();
    scatter_kernel<<<eb, 256>>>(src, dst, E);

    transform0_kernel<<<nb, 256>>>(x, W[0], asr[0], adt[0], hA);

    int gb = (NNODES * 3 + 383) / 384;
    gather_head_kernel<<<gb, 384>>>(hA, b[0]);
    transform_mid_kernel<<<nb, 256>>>(W[1], asr[1], adt[1], hB);
    gather_head_kernel<<<gb, 384>>>(hB, b[1]);
    transform_mid_kernel<<<nb, 256>>>(W[2], asr[2], adt[2], hA);
    gather_head_kernel<<<gb, 384>>>(hA, b[2]);
    transform_mid_kernel<<<nb, 256>>>(W[3], asr[3], adt[3], hB);
    gather_head_last_kernel<<<gb, 384>>>(hB);
    final_kernel<<<nb, 256>>>(b[3], lin1_w, lin1_b, lin2_w, lin2_b, out);
}